// round 15
// baseline (speedup 1.0000x reference)
#include <cuda_runtime.h>
#include <cuda_fp16.h>
#include <cstdint>

#define SEQC 2048
#define BATCHC 4
#define NHEAD 16
#define DMOD 1024
#define MTOT (BATCHC * SEQC)     // 8192
#define QSZ (MTOT * DMOD)        // 8388608 elems per Q/K/V tensor

__device__ __half g_xf[MTOT * DMOD];
__device__ __half g_wf[4 * DMOD * DMOD];
__device__ __half g_qkv[3 * QSZ];
__device__ __half g_ao[MTOT * DMOD];

// ------------------------------ helpers -------------------------------------
__device__ __forceinline__ uint32_t su32(const void* p) {
    uint32_t a;
    asm("{ .reg .u64 t; cvta.to.shared.u64 t, %1; cvt.u32.u64 %0, t; }" : "=r"(a) : "l"(p));
    return a;
}
__device__ __forceinline__ uint32_t pk2h(float e0, float e1) {      // f16x2
    uint32_t d;
    asm("cvt.rn.f16x2.f32 %0, %1, %2;" : "=r"(d) : "f"(e1), "f"(e0));
    return d;
}
__device__ __forceinline__ void ldsm4(uint32_t& r0, uint32_t& r1, uint32_t& r2,
                                      uint32_t& r3, uint32_t a) {
    asm volatile("ldmatrix.sync.aligned.m8n8.x4.shared.b16 {%0,%1,%2,%3}, [%4];"
                 : "=r"(r0), "=r"(r1), "=r"(r2), "=r"(r3) : "r"(a));
}
__device__ __forceinline__ void ldsm4t(uint32_t& r0, uint32_t& r1, uint32_t& r2,
                                       uint32_t& r3, uint32_t a) {
    asm volatile("ldmatrix.sync.aligned.m8n8.x4.trans.shared.b16 {%0,%1,%2,%3}, [%4];"
                 : "=r"(r0), "=r"(r1), "=r"(r2), "=r"(r3) : "r"(a));
}
__device__ __forceinline__ void mmah(float* c, const uint32_t* a, const uint32_t* b) {
    asm volatile(
        "mma.sync.aligned.m16n8k16.row.col.f32.f16.f16.f32 "
        "{%0,%1,%2,%3},{%4,%5,%6,%7},{%8,%9},{%0,%1,%2,%3};"
        : "+f"(c[0]), "+f"(c[1]), "+f"(c[2]), "+f"(c[3])
        : "r"(a[0]), "r"(a[1]), "r"(a[2]), "r"(a[3]), "r"(b[0]), "r"(b[1]));
}
#define CP_ASYNC(dst, src) \
    asm volatile("cp.async.cg.shared.global [%0], [%1], 16;" :: "r"(dst), "l"(src) : "memory")
#define CP_COMMIT() asm volatile("cp.async.commit_group;" ::: "memory")
#define CP_WAIT(n)  asm volatile("cp.async.wait_group %0;" :: "n"(n) : "memory")

// --------------- fp32 -> fp16 convert, ALL tensors in one launch -------------
#define N4X (MTOT * DMOD / 4)
#define N4W (DMOD * DMOD / 4)

__global__ void split_all(const float4* __restrict__ x,
                          const float4* __restrict__ w0, const float4* __restrict__ w1,
                          const float4* __restrict__ w2, const float4* __restrict__ w3,
                          uint2* __restrict__ xf, uint2* __restrict__ wf) {
    int i = blockIdx.x * blockDim.x + threadIdx.x;
    const float4* src;
    uint2* dst;
    int off;
    if (i < N4X) {
        src = x; dst = xf; off = i;
    } else {
        int j = i - N4X;
        int wsel = j >> 18;
        off = j & (N4W - 1);
        src = (wsel == 0) ? w0 : (wsel == 1) ? w1 : (wsel == 2) ? w2 : w3;
        dst = wf + (size_t)wsel * N4W;
    }
    float4 v = src[off];
    dst[off] = make_uint2(pk2h(v.x, v.y), pk2h(v.z, v.w));
}

// ---------- GEMM: fp16, BK=64, 3-stage ring, ONE barrier per iter ------------
#define GPB 144                   // 64 fp16 = 128B + 16B pad per row
#define ARR (128 * GPB)           // 18432 per array
#define BUF (2 * ARR)             // 36864 per stage

template <int MODE>                  // 1: fp16 QKV out (headsplit), 0: fp32 out
__global__ __launch_bounds__(256, 2) void gemm_h(const __half* __restrict__ A,
                                                 const __half* __restrict__ B,
                                                 float* __restrict__ C,
                                                 uint32_t* __restrict__ Oh) {
    extern __shared__ char sm[];
    const uint32_t sb = su32(sm);
    const int tid = threadIdx.x, lane = tid & 31, wid = tid >> 5;
    const int m0 = blockIdx.y * 128, n0 = blockIdx.x * 128;
    const int wm = (wid >> 2) * 64, wn = (wid & 3) * 32;

    auto fill = [&](int kb, int buf) {
        uint32_t base = sb + buf * BUF;
#pragma unroll
        for (int i = 0; i < 4; i++) {
            int idx = tid + i * 256;          // 0..1023
            int row = idx >> 3, c8 = idx & 7;
            uint32_t off = (uint32_t)row * GPB + c8 * 16;
            CP_ASYNC(base + 0 * ARR + off, A + (size_t)(m0 + row) * 1024 + kb + c8 * 8);
            CP_ASYNC(base + 1 * ARR + off, B + (size_t)(n0 + row) * 1024 + kb + c8 * 8);
        }
        CP_COMMIT();
    };

    float acc[4][4][4];
#pragma unroll
    for (int i = 0; i < 4; i++)
#pragma unroll
        for (int j = 0; j < 4; j++)
#pragma unroll
            for (int e = 0; e < 4; e++) acc[i][j][e] = 0.f;

    fill(0, 0);
    fill(64, 1);
    for (int t = 0; t < 16; t++) {
        if (t == 15) { CP_WAIT(0); }
        else         { CP_WAIT(1); }       // oldest (group t) complete
        __syncthreads();                   // single barrier per iteration
        if (t + 2 < 16) fill((t + 2) * 64, (t + 2) % 3);

        const uint32_t bb = sb + (uint32_t)(t % 3) * BUF;
#pragma unroll
        for (int s = 0; s < 4; s++) {
            uint32_t ah[4][4];
            const int arow = wm + (lane & 15);
            const int acol = s * 16 + (lane >> 4) * 8;
#pragma unroll
            for (int i = 0; i < 4; i++) {
                uint32_t off = (uint32_t)(arow + i * 16) * GPB + acol * 2;
                ldsm4(ah[i][0], ah[i][1], ah[i][2], ah[i][3], bb + 0 * ARR + off);
            }
            const int g = lane >> 3;
            const int brow = wn + (g >> 1) * 8 + (lane & 7);
            const int bcol = s * 16 + (g & 1) * 8;
#pragma unroll
            for (int p = 0; p < 2; p++) {
                uint32_t bh[4];
                uint32_t off = (uint32_t)(brow + p * 16) * GPB + bcol * 2;
                ldsm4(bh[0], bh[1], bh[2], bh[3], bb + 1 * ARR + off);
#pragma unroll
                for (int i = 0; i < 4; i++) mmah(acc[i][2 * p],     ah[i], &bh[0]);
#pragma unroll
                for (int i = 0; i < 4; i++) mmah(acc[i][2 * p + 1], ah[i], &bh[2]);
            }
        }
    }

    const int r0 = m0 + wm + (lane >> 2);
    const int cb = n0 + wn + (lane & 3) * 2;
#pragma unroll
    for (int i = 0; i < 4; i++) {
#pragma unroll
        for (int half = 0; half < 2; half++) {
            int r = r0 + i * 16 + half * 8;
#pragma unroll
            for (int j = 0; j < 4; j++) {
                int c = cb + j * 8;
                float e0 = half ? acc[i][j][2] : acc[i][j][0];
                float e1 = half ? acc[i][j][3] : acc[i][j][1];
                if (MODE == 1) {
                    int which = c >> 10, cc = c & 1023;
                    int h = cc >> 6, dk = cc & 63;
                    int b = r >> 11, sdx = r & 2047;
                    size_t idx = (size_t)which * QSZ +
                                 ((((size_t)b * NHEAD + h) * SEQC + sdx) << 6) + dk;
                    Oh[idx >> 1] = pk2h(e0, e1);
                } else {
                    *(float2*)&C[(size_t)r * 1024 + c] = make_float2(e0, e1);
                }
            }
        }
    }
}

// ------- flash attention, fp16 mma, causal; 128-row KV stages ----------------
#define AP 144
#define KVHALF (64 * AP)          // 9216: one 64-row sub-tile of K or V
#define KV128 (128 * AP)          // 18432: full 128-row K (or V) array
#define STG (2 * KV128)           // 36864 per stage (K128 + V128)
#define QREGA (128 * AP)          // 18432 fp16 Q tile

__global__ void attn_mma(const __half* __restrict__ QKV,
                         uint32_t* __restrict__ AO) {
    extern __shared__ char smc[];
    const uint32_t sb = su32(smc);
    const int tid = threadIdx.x, lane = tid & 31, w = tid >> 5;
    const int qt = blockIdx.x, bh = blockIdx.y;
    const int q0 = qt * 128;
    const int b = bh >> 4, h = bh & 15;

    const size_t bhoff = (size_t)bh * SEQC * 64;
    const __half *Q = QKV + bhoff;
    const __half *K = QKV + QSZ + bhoff;
    const __half *V = QKV + 2 * QSZ + bhoff;

    // fill one 128-row KV stage
    auto fillkv = [&](int t, int buf) {
        uint32_t base = sb + QREGA + buf * STG;
#pragma unroll
        for (int i = 0; i < 4; i++) {
            int idx = tid + i * 256;           // 0..1023
            int row = idx >> 3, c8 = idx & 7;
            uint32_t off = (uint32_t)row * AP + c8 * 16;
            size_t go = (size_t)(t * 128 + row) * 64 + c8 * 8;
            CP_ASYNC(base + off, K + go);
            CP_ASYNC(base + KV128 + off, V + go);
        }
        CP_COMMIT();
    };

    fillkv(0, 0);
#pragma unroll
    for (int i = 0; i < 4; i++) {
        int idx = tid + i * 256;
        int row = idx >> 3, c8 = idx & 7;
        uint32_t off = (uint32_t)row * AP + c8 * 16;
        *(uint4*)(smc + off) = *(const uint4*)(Q + (size_t)(q0 + row) * 64 + c8 * 8);
    }
    __syncthreads();

    uint32_t qh[4][4];
    {
        const int arow = w * 16 + (lane & 15);
#pragma unroll
        for (int s = 0; s < 4; s++) {
            uint32_t off = (uint32_t)arow * AP + (s * 16 + (lane >> 4) * 8) * 2;
            ldsm4(qh[s][0], qh[s][1], qh[s][2], qh[s][3], sb + off);
        }
    }

    float o[8][4];
#pragma unroll
    for (int j = 0; j < 8; j++)
#pragma unroll
        for (int e = 0; e < 4; e++) o[j][e] = 0.f;
    float m_lo = -1e30f, m_hi = -1e30f, l_lo = 0.f, l_hi = 0.f;

    const int rlo = q0 + w * 16 + (lane >> 2);
    const int rhi = rlo + 8;
    const int g = lane >> 3;

    for (int t = 0; t <= qt; t++) {
        if (t + 1 <= qt) { fillkv(t + 1, (t + 1) & 1); CP_WAIT(1); }
        else             { CP_WAIT(0); }
        __syncthreads();

        const uint32_t bbase = sb + QREGA + (uint32_t)(t & 1) * STG;

        // two 64-column sub-tiles per staged 128 KV rows (no barrier between)
#pragma unroll
        for (int u = 0; u < 2; u++) {
            const uint32_t Ko = bbase + u * KVHALF;
            const uint32_t Vo = bbase + KV128 + u * KVHALF;
            const int c64 = 2 * t + u;

            float s_[8][4];
#pragma unroll
            for (int j = 0; j < 8; j++)
#pragma unroll
                for (int e = 0; e < 4; e++) s_[j][e] = 0.f;

#pragma unroll
            for (int s = 0; s < 4; s++) {
                const int brow = (g >> 1) * 8 + (lane & 7);
                const int bcol = s * 16 + (g & 1) * 8;
                uint32_t kh[4][4];
#pragma unroll
                for (int p = 0; p < 4; p++) {
                    uint32_t off = (uint32_t)(brow + p * 16) * AP + bcol * 2;
                    ldsm4(kh[p][0], kh[p][1], kh[p][2], kh[p][3], Ko + off);
                }
#pragma unroll
                for (int p = 0; p < 4; p++) {
                    mmah(s_[2 * p],     qh[s], &kh[p][0]);
                    mmah(s_[2 * p + 1], qh[s], &kh[p][2]);
                }
            }

            const bool msk = (c64 >= 2 * qt);
#pragma unroll
            for (int j = 0; j < 8; j++) {
                int c = c64 * 64 + j * 8 + (lane & 3) * 2;
#pragma unroll
                for (int e = 0; e < 4; e++) s_[j][e] *= 0.125f;
                if (msk) {
                    if (c > rlo)     s_[j][0] = -1e30f;
                    if (c + 1 > rlo) s_[j][1] = -1e30f;
                    if (c > rhi)     s_[j][2] = -1e30f;
                    if (c + 1 > rhi) s_[j][3] = -1e30f;
                }
            }

            float rm_lo = -1e30f, rm_hi = -1e30f;
#pragma unroll
            for (int j = 0; j < 8; j++) {
                rm_lo = fmaxf(rm_lo, fmaxf(s_[j][0], s_[j][1]));
                rm_hi = fmaxf(rm_hi, fmaxf(s_[j][2], s_[j][3]));
            }
            rm_lo = fmaxf(rm_lo, __shfl_xor_sync(0xffffffffu, rm_lo, 1));
            rm_lo = fmaxf(rm_lo, __shfl_xor_sync(0xffffffffu, rm_lo, 2));
            rm_hi = fmaxf(rm_hi, __shfl_xor_sync(0xffffffffu, rm_hi, 1));
            rm_hi = fmaxf(rm_hi, __shfl_xor_sync(0xffffffffu, rm_hi, 2));
            float mn_lo = fmaxf(m_lo, rm_lo), mn_hi = fmaxf(m_hi, rm_hi);
            float cor_lo = __expf(m_lo - mn_lo), cor_hi = __expf(m_hi - mn_hi);
            m_lo = mn_lo; m_hi = mn_hi;
            float sum_lo = 0.f, sum_hi = 0.f;
#pragma unroll
            for (int j = 0; j < 8; j++) {
                s_[j][0] = __expf(s_[j][0] - mn_lo); sum_lo += s_[j][0];
                s_[j][1] = __expf(s_[j][1] - mn_lo); sum_lo += s_[j][1];
                s_[j][2] = __expf(s_[j][2] - mn_hi); sum_hi += s_[j][2];
                s_[j][3] = __expf(s_[j][3] - mn_hi); sum_hi += s_[j][3];
            }
            sum_lo += __shfl_xor_sync(0xffffffffu, sum_lo, 1);
            sum_lo += __shfl_xor_sync(0xffffffffu, sum_lo, 2);
            sum_hi += __shfl_xor_sync(0xffffffffu, sum_hi, 1);
            sum_hi += __shfl_xor_sync(0xffffffffu, sum_hi, 2);
            l_lo = l_lo * cor_lo + sum_lo;
            l_hi = l_hi * cor_hi + sum_hi;
#pragma unroll
            for (int j = 0; j < 8; j++) {
                o[j][0] *= cor_lo; o[j][1] *= cor_lo;
                o[j][2] *= cor_hi; o[j][3] *= cor_hi;
            }

#pragma unroll
            for (int s = 0; s < 4; s++) {
                uint32_t ph[4];
                ph[0] = pk2h(s_[2 * s][0],     s_[2 * s][1]);
                ph[1] = pk2h(s_[2 * s][2],     s_[2 * s][3]);
                ph[2] = pk2h(s_[2 * s + 1][0], s_[2 * s + 1][1]);
                ph[3] = pk2h(s_[2 * s + 1][2], s_[2 * s + 1][3]);
                const int kvr = s * 16 + (g & 1) * 8 + (lane & 7);
                uint32_t vh[4][4];
#pragma unroll
                for (int p = 0; p < 4; p++) {
                    uint32_t off = (uint32_t)kvr * AP + ((g >> 1) * 8 + p * 16) * 2;
                    ldsm4t(vh[p][0], vh[p][1], vh[p][2], vh[p][3], Vo + off);
                }
#pragma unroll
                for (int p = 0; p < 4; p++) {
                    mmah(o[2 * p],     ph, &vh[p][0]);
                    mmah(o[2 * p + 1], ph, &vh[p][2]);
                }
            }
        }
        __syncthreads();   // stage (t&1) free for refill at iter t+1
    }

    const float il_lo = 1.f / l_lo, il_hi = 1.f / l_hi;
    const int colb = h * 64 + (lane & 3) * 2;
#pragma unroll
    for (int j = 0; j < 8; j++) {
        int col = colb + j * 8;
        size_t ilo = ((size_t)(b * SEQC + rlo) * DMOD + col);
        size_t ihi = ((size_t)(b * SEQC + rhi) * DMOD + col);
        AO[ilo >> 1] = pk2h(o[j][0] * il_lo, o[j][1] * il_lo);
        AO[ihi >> 1] = pk2h(o[j][2] * il_hi, o[j][3] * il_hi);
    }
}

// ------------------------------ launch --------------------------------------
extern "C" void kernel_launch(void* const* d_in, const int* in_sizes, int n_in,
                              void* d_out, int out_size) {
    const float* x = (const float*)d_in[0];
    float* out = (float*)d_out;

    __half *xf, *wf, *qkv, *ao;
    cudaGetSymbolAddress((void**)&xf, g_xf);
    cudaGetSymbolAddress((void**)&wf, g_wf);
    cudaGetSymbolAddress((void**)&qkv, g_qkv);
    cudaGetSymbolAddress((void**)&ao, g_ao);

    const int NW = DMOD * DMOD;

    split_all<<<(N4X + 4 * N4W + 255) / 256, 256>>>(
        (const float4*)x, (const float4*)d_in[1], (const float4*)d_in[2],
        (const float4*)d_in[3], (const float4*)d_in[4],
        (uint2*)xf, (uint2*)wf);

    const int gshm = 3 * BUF;   // 110592 (3-stage ring)
    cudaFuncSetAttribute(gemm_h<1>, cudaFuncAttributeMaxDynamicSharedMemorySize, gshm);
    cudaFuncSetAttribute(gemm_h<0>, cudaFuncAttributeMaxDynamicSharedMemorySize, gshm);

    // fused QKV projection: N = 3072, fp16 output
    gemm_h<1><<<dim3(24, 64), 256, gshm>>>(xf, wf, nullptr, (uint32_t*)qkv);

    const int ashm = QREGA + 2 * STG;   // 92160
    cudaFuncSetAttribute(attn_mma, cudaFuncAttributeMaxDynamicSharedMemorySize, ashm);
    attn_mma<<<dim3(SEQC / 128, BATCHC * NHEAD), 256, ashm>>>(qkv, (uint32_t*)ao);

    gemm_h<0><<<dim3(8, 64), 256, gshm>>>(ao, wf + (size_t)3 * NW, out, nullptr);
}

// round 16
// speedup vs baseline: 1.1325x; 1.1325x over previous
#include <cuda_runtime.h>
#include <cuda_fp16.h>
#include <cstdint>

#define SEQC 2048
#define BATCHC 4
#define NHEAD 16
#define DMOD 1024
#define MTOT (BATCHC * SEQC)     // 8192
#define QSZ (MTOT * DMOD)        // 8388608 elems per Q/K/V tensor

__device__ __half g_xf[MTOT * DMOD];
__device__ __half g_wf[4 * DMOD * DMOD];
__device__ __half g_qkv[3 * QSZ];
__device__ __half g_ao[MTOT * DMOD];

// ------------------------------ helpers -------------------------------------
__device__ __forceinline__ uint32_t su32(const void* p) {
    uint32_t a;
    asm("{ .reg .u64 t; cvta.to.shared.u64 t, %1; cvt.u32.u64 %0, t; }" : "=r"(a) : "l"(p));
    return a;
}
__device__ __forceinline__ uint32_t pk2h(float e0, float e1) {      // f16x2
    uint32_t d;
    asm("cvt.rn.f16x2.f32 %0, %1, %2;" : "=r"(d) : "f"(e1), "f"(e0));
    return d;
}
__device__ __forceinline__ void ldsm4(uint32_t& r0, uint32_t& r1, uint32_t& r2,
                                      uint32_t& r3, uint32_t a) {
    asm volatile("ldmatrix.sync.aligned.m8n8.x4.shared.b16 {%0,%1,%2,%3}, [%4];"
                 : "=r"(r0), "=r"(r1), "=r"(r2), "=r"(r3) : "r"(a));
}
__device__ __forceinline__ void ldsm4t(uint32_t& r0, uint32_t& r1, uint32_t& r2,
                                       uint32_t& r3, uint32_t a) {
    asm volatile("ldmatrix.sync.aligned.m8n8.x4.trans.shared.b16 {%0,%1,%2,%3}, [%4];"
                 : "=r"(r0), "=r"(r1), "=r"(r2), "=r"(r3) : "r"(a));
}
__device__ __forceinline__ void mmah(float* c, const uint32_t* a, const uint32_t* b) {
    asm volatile(
        "mma.sync.aligned.m16n8k16.row.col.f32.f16.f16.f32 "
        "{%0,%1,%2,%3},{%4,%5,%6,%7},{%8,%9},{%0,%1,%2,%3};"
        : "+f"(c[0]), "+f"(c[1]), "+f"(c[2]), "+f"(c[3])
        : "r"(a[0]), "r"(a[1]), "r"(a[2]), "r"(a[3]), "r"(b[0]), "r"(b[1]));
}
#define CP_ASYNC(dst, src) \
    asm volatile("cp.async.cg.shared.global [%0], [%1], 16;" :: "r"(dst), "l"(src) : "memory")
#define CP_COMMIT() asm volatile("cp.async.commit_group;" ::: "memory")
#define CP_WAIT(n)  asm volatile("cp.async.wait_group %0;" :: "n"(n) : "memory")

// --------------- fp32 -> fp16 convert, ALL tensors in one launch -------------
#define N4X (MTOT * DMOD / 4)
#define N4W (DMOD * DMOD / 4)

__global__ void split_all(const float4* __restrict__ x,
                          const float4* __restrict__ w0, const float4* __restrict__ w1,
                          const float4* __restrict__ w2, const float4* __restrict__ w3,
                          uint2* __restrict__ xf, uint2* __restrict__ wf) {
    int i = blockIdx.x * blockDim.x + threadIdx.x;
    const float4* src;
    uint2* dst;
    int off;
    if (i < N4X) {
        src = x; dst = xf; off = i;
    } else {
        int j = i - N4X;
        int wsel = j >> 18;
        off = j & (N4W - 1);
        src = (wsel == 0) ? w0 : (wsel == 1) ? w1 : (wsel == 2) ? w2 : w3;
        dst = wf + (size_t)wsel * N4W;
    }
    float4 v = src[off];
    dst[off] = make_uint2(pk2h(v.x, v.y), pk2h(v.z, v.w));
}

// ---------- GEMM: C[M,N] = A[M,1024] B[N,1024]^T, fp16, BK=64 (R14) ----------
#define GPB 144                   // 64 fp16 = 128B + 16B pad per row
#define ARR (128 * GPB)           // 18432 per array
#define BUF (2 * ARR)             // 36864 per stage

template <int MODE>                  // 1: fp16 QKV out (headsplit), 0: fp32 out
__global__ __launch_bounds__(256, 2) void gemm_h(const __half* __restrict__ A,
                                                 const __half* __restrict__ B,
                                                 float* __restrict__ C,
                                                 uint32_t* __restrict__ Oh) {
    extern __shared__ char sm[];
    const uint32_t sb = su32(sm);
    const int tid = threadIdx.x, lane = tid & 31, wid = tid >> 5;
    const int m0 = blockIdx.y * 128, n0 = blockIdx.x * 128;
    const int wm = (wid >> 2) * 64, wn = (wid & 3) * 32;

    auto fill = [&](int kb, int buf) {
        uint32_t base = sb + buf * BUF;
#pragma unroll
        for (int i = 0; i < 4; i++) {
            int idx = tid + i * 256;          // 0..1023
            int row = idx >> 3, c8 = idx & 7;
            uint32_t off = (uint32_t)row * GPB + c8 * 16;
            CP_ASYNC(base + 0 * ARR + off, A + (size_t)(m0 + row) * 1024 + kb + c8 * 8);
            CP_ASYNC(base + 1 * ARR + off, B + (size_t)(n0 + row) * 1024 + kb + c8 * 8);
        }
        CP_COMMIT();
    };

    float acc[4][4][4];
#pragma unroll
    for (int i = 0; i < 4; i++)
#pragma unroll
        for (int j = 0; j < 4; j++)
#pragma unroll
            for (int e = 0; e < 4; e++) acc[i][j][e] = 0.f;

    fill(0, 0);
    for (int t = 0; t < 16; t++) {
        if (t + 1 < 16) { fill((t + 1) * 64, (t + 1) & 1); CP_WAIT(1); }
        else            { CP_WAIT(0); }
        __syncthreads();

        const uint32_t bb = sb + (t & 1) * BUF;
#pragma unroll
        for (int s = 0; s < 4; s++) {
            uint32_t ah[4][4];
            const int arow = wm + (lane & 15);
            const int acol = s * 16 + (lane >> 4) * 8;
#pragma unroll
            for (int i = 0; i < 4; i++) {
                uint32_t off = (uint32_t)(arow + i * 16) * GPB + acol * 2;
                ldsm4(ah[i][0], ah[i][1], ah[i][2], ah[i][3], bb + 0 * ARR + off);
            }
            const int g = lane >> 3;
            const int brow = wn + (g >> 1) * 8 + (lane & 7);
            const int bcol = s * 16 + (g & 1) * 8;
#pragma unroll
            for (int p = 0; p < 2; p++) {
                uint32_t bh[4];
                uint32_t off = (uint32_t)(brow + p * 16) * GPB + bcol * 2;
                ldsm4(bh[0], bh[1], bh[2], bh[3], bb + 1 * ARR + off);
#pragma unroll
                for (int i = 0; i < 4; i++) mmah(acc[i][2 * p],     ah[i], &bh[0]);
#pragma unroll
                for (int i = 0; i < 4; i++) mmah(acc[i][2 * p + 1], ah[i], &bh[2]);
            }
        }
        __syncthreads();
    }

    const int r0 = m0 + wm + (lane >> 2);
    const int cb = n0 + wn + (lane & 3) * 2;
#pragma unroll
    for (int i = 0; i < 4; i++) {
#pragma unroll
        for (int half = 0; half < 2; half++) {
            int r = r0 + i * 16 + half * 8;
#pragma unroll
            for (int j = 0; j < 4; j++) {
                int c = cb + j * 8;
                float e0 = half ? acc[i][j][2] : acc[i][j][0];
                float e1 = half ? acc[i][j][3] : acc[i][j][1];
                if (MODE == 1) {
                    int which = c >> 10, cc = c & 1023;
                    int h = cc >> 6, dk = cc & 63;
                    int b = r >> 11, sdx = r & 2047;
                    size_t idx = (size_t)which * QSZ +
                                 ((((size_t)b * NHEAD + h) * SEQC + sdx) << 6) + dk;
                    Oh[idx >> 1] = pk2h(e0, e1);
                } else {
                    *(float2*)&C[(size_t)r * 1024 + c] = make_float2(e0, e1);
                }
            }
        }
    }
}

// ------ flash attention, fp16 mma, causal (R14 body) + LPT heavy-first -------
#define AP 144
#define KVARR (64 * AP)          // 9216 per K or V array
#define STG (2 * KVARR)          // 18432 per KV stage
#define QREGA (128 * AP)         // 18432 fp16 Q tile

__global__ void attn_mma(const __half* __restrict__ QKV,
                         uint32_t* __restrict__ AO) {
    extern __shared__ char smc[];
    const uint32_t sb = su32(smc);
    const int tid = threadIdx.x, lane = tid & 31, w = tid >> 5;
    // LPT schedule: heaviest q-tiles (largest qt) launch first across all bh
    const int idx0 = blockIdx.x;
    const int qt = (SEQC / 128 - 1) - (idx0 >> 6);   // 15,15,...,14,...,0
    const int bh = idx0 & 63;
    const int q0 = qt * 128;
    const int b = bh >> 4, h = bh & 15;

    const size_t bhoff = (size_t)bh * SEQC * 64;
    const __half *Q = QKV + bhoff;
    const __half *K = QKV + QSZ + bhoff;
    const __half *V = QKV + 2 * QSZ + bhoff;

    auto fillkv = [&](int t, int buf) {
        uint32_t base = sb + QREGA + buf * STG;
#pragma unroll
        for (int i = 0; i < 2; i++) {
            int idx = tid + i * 256;
            int row = idx >> 3, c8 = idx & 7;
            uint32_t off = (uint32_t)row * AP + c8 * 16;
            size_t go = (size_t)(t * 64 + row) * 64 + c8 * 8;
            CP_ASYNC(base + 0 * KVARR + off, K + go);
            CP_ASYNC(base + 1 * KVARR + off, V + go);
        }
        CP_COMMIT();
    };

    fillkv(0, 0);
#pragma unroll
    for (int i = 0; i < 4; i++) {
        int idx = tid + i * 256;
        int row = idx >> 3, c8 = idx & 7;
        uint32_t off = (uint32_t)row * AP + c8 * 16;
        *(uint4*)(smc + off) = *(const uint4*)(Q + (size_t)(q0 + row) * 64 + c8 * 8);
    }
    __syncthreads();

    uint32_t qh[4][4];
    {
        const int arow = w * 16 + (lane & 15);
#pragma unroll
        for (int s = 0; s < 4; s++) {
            uint32_t off = (uint32_t)arow * AP + (s * 16 + (lane >> 4) * 8) * 2;
            ldsm4(qh[s][0], qh[s][1], qh[s][2], qh[s][3], sb + off);
        }
    }

    float o[8][4];
#pragma unroll
    for (int j = 0; j < 8; j++)
#pragma unroll
        for (int e = 0; e < 4; e++) o[j][e] = 0.f;
    float m_lo = -1e30f, m_hi = -1e30f, l_lo = 0.f, l_hi = 0.f;

    const int rlo = q0 + w * 16 + (lane >> 2);
    const int rhi = rlo + 8;
    const int g = lane >> 3;
    const int tmax = 2 * qt + 1;

    for (int t = 0; t <= tmax; t++) {
        if (t + 1 <= tmax) { fillkv(t + 1, (t + 1) & 1); CP_WAIT(1); }
        else               { CP_WAIT(0); }
        __syncthreads();

        const uint32_t bbase = sb + QREGA + (uint32_t)(t & 1) * STG;
        const uint32_t Ko = bbase, Vo = bbase + KVARR;

        float s_[8][4];
#pragma unroll
        for (int j = 0; j < 8; j++)
#pragma unroll
            for (int e = 0; e < 4; e++) s_[j][e] = 0.f;

#pragma unroll
        for (int s = 0; s < 4; s++) {
            const int brow = (g >> 1) * 8 + (lane & 7);
            const int bcol = s * 16 + (g & 1) * 8;
            uint32_t kh[4][4];
#pragma unroll
            for (int p = 0; p < 4; p++) {
                uint32_t off = (uint32_t)(brow + p * 16) * AP + bcol * 2;
                ldsm4(kh[p][0], kh[p][1], kh[p][2], kh[p][3], Ko + off);
            }
#pragma unroll
            for (int p = 0; p < 4; p++) {
                mmah(s_[2 * p],     qh[s], &kh[p][0]);
                mmah(s_[2 * p + 1], qh[s], &kh[p][2]);
            }
        }

        const bool msk = (t >= 2 * qt);
#pragma unroll
        for (int j = 0; j < 8; j++) {
            int c = t * 64 + j * 8 + (lane & 3) * 2;
#pragma unroll
            for (int e = 0; e < 4; e++) s_[j][e] *= 0.125f;
            if (msk) {
                if (c > rlo)     s_[j][0] = -1e30f;
                if (c + 1 > rlo) s_[j][1] = -1e30f;
                if (c > rhi)     s_[j][2] = -1e30f;
                if (c + 1 > rhi) s_[j][3] = -1e30f;
            }
        }

        float rm_lo = -1e30f, rm_hi = -1e30f;
#pragma unroll
        for (int j = 0; j < 8; j++) {
            rm_lo = fmaxf(rm_lo, fmaxf(s_[j][0], s_[j][1]));
            rm_hi = fmaxf(rm_hi, fmaxf(s_[j][2], s_[j][3]));
        }
        rm_lo = fmaxf(rm_lo, __shfl_xor_sync(0xffffffffu, rm_lo, 1));
        rm_lo = fmaxf(rm_lo, __shfl_xor_sync(0xffffffffu, rm_lo, 2));
        rm_hi = fmaxf(rm_hi, __shfl_xor_sync(0xffffffffu, rm_hi, 1));
        rm_hi = fmaxf(rm_hi, __shfl_xor_sync(0xffffffffu, rm_hi, 2));
        float mn_lo = fmaxf(m_lo, rm_lo), mn_hi = fmaxf(m_hi, rm_hi);
        float cor_lo = __expf(m_lo - mn_lo), cor_hi = __expf(m_hi - mn_hi);
        m_lo = mn_lo; m_hi = mn_hi;
        float sum_lo = 0.f, sum_hi = 0.f;
#pragma unroll
        for (int j = 0; j < 8; j++) {
            s_[j][0] = __expf(s_[j][0] - mn_lo); sum_lo += s_[j][0];
            s_[j][1] = __expf(s_[j][1] - mn_lo); sum_lo += s_[j][1];
            s_[j][2] = __expf(s_[j][2] - mn_hi); sum_hi += s_[j][2];
            s_[j][3] = __expf(s_[j][3] - mn_hi); sum_hi += s_[j][3];
        }
        sum_lo += __shfl_xor_sync(0xffffffffu, sum_lo, 1);
        sum_lo += __shfl_xor_sync(0xffffffffu, sum_lo, 2);
        sum_hi += __shfl_xor_sync(0xffffffffu, sum_hi, 1);
        sum_hi += __shfl_xor_sync(0xffffffffu, sum_hi, 2);
        l_lo = l_lo * cor_lo + sum_lo;
        l_hi = l_hi * cor_hi + sum_hi;
#pragma unroll
        for (int j = 0; j < 8; j++) {
            o[j][0] *= cor_lo; o[j][1] *= cor_lo;
            o[j][2] *= cor_hi; o[j][3] *= cor_hi;
        }

#pragma unroll
        for (int s = 0; s < 4; s++) {
            uint32_t ph[4];
            ph[0] = pk2h(s_[2 * s][0],     s_[2 * s][1]);
            ph[1] = pk2h(s_[2 * s][2],     s_[2 * s][3]);
            ph[2] = pk2h(s_[2 * s + 1][0], s_[2 * s + 1][1]);
            ph[3] = pk2h(s_[2 * s + 1][2], s_[2 * s + 1][3]);
            const int kvr = s * 16 + (g & 1) * 8 + (lane & 7);
            uint32_t vh[4][4];
#pragma unroll
            for (int p = 0; p < 4; p++) {
                uint32_t off = (uint32_t)kvr * AP + ((g >> 1) * 8 + p * 16) * 2;
                ldsm4t(vh[p][0], vh[p][1], vh[p][2], vh[p][3], Vo + off);
            }
#pragma unroll
            for (int p = 0; p < 4; p++) {
                mmah(o[2 * p],     ph, &vh[p][0]);
                mmah(o[2 * p + 1], ph, &vh[p][2]);
            }
        }
        __syncthreads();
    }

    const float il_lo = 1.f / l_lo, il_hi = 1.f / l_hi;
    const int colb = h * 64 + (lane & 3) * 2;
#pragma unroll
    for (int j = 0; j < 8; j++) {
        int col = colb + j * 8;
        size_t ilo = ((size_t)(b * SEQC + rlo) * DMOD + col);
        size_t ihi = ((size_t)(b * SEQC + rhi) * DMOD + col);
        AO[ilo >> 1] = pk2h(o[j][0] * il_lo, o[j][1] * il_lo);
        AO[ihi >> 1] = pk2h(o[j][2] * il_hi, o[j][3] * il_hi);
    }
}

// ------------------------------ launch --------------------------------------
extern "C" void kernel_launch(void* const* d_in, const int* in_sizes, int n_in,
                              void* d_out, int out_size) {
    const float* x = (const float*)d_in[0];
    float* out = (float*)d_out;

    __half *xf, *wf, *qkv, *ao;
    cudaGetSymbolAddress((void**)&xf, g_xf);
    cudaGetSymbolAddress((void**)&wf, g_wf);
    cudaGetSymbolAddress((void**)&qkv, g_qkv);
    cudaGetSymbolAddress((void**)&ao, g_ao);

    const int NW = DMOD * DMOD;

    split_all<<<(N4X + 4 * N4W + 255) / 256, 256>>>(
        (const float4*)x, (const float4*)d_in[1], (const float4*)d_in[2],
        (const float4*)d_in[3], (const float4*)d_in[4],
        (uint2*)xf, (uint2*)wf);

    const int gshm = 2 * BUF;   // 73728
    cudaFuncSetAttribute(gemm_h<1>, cudaFuncAttributeMaxDynamicSharedMemorySize, gshm);
    cudaFuncSetAttribute(gemm_h<0>, cudaFuncAttributeMaxDynamicSharedMemorySize, gshm);

    // fused QKV projection: N = 3072, fp16 output
    gemm_h<1><<<dim3(24, 64), 256, gshm>>>(xf, wf, nullptr, (uint32_t*)qkv);

    const int ashm = QREGA + 2 * STG;   // 55296
    cudaFuncSetAttribute(attn_mma, cudaFuncAttributeMaxDynamicSharedMemorySize, ashm);
    // 1D grid, LPT heavy-first decode inside the kernel
    attn_mma<<<(SEQC / 128) * BATCHC * NHEAD, 256, ashm>>>(qkv, (uint32_t*)ao);

    gemm_h<0><<<dim3(8, 64), 256, gshm>>>(ao, wf + (size_t)3 * NW, out, nullptr);
}

// round 17
// speedup vs baseline: 1.1473x; 1.0131x over previous
#include <cuda_runtime.h>
#include <cuda_fp16.h>
#include <cstdint>

#define SEQC 2048
#define BATCHC 4
#define NHEAD 16
#define DMOD 1024
#define MTOT (BATCHC * SEQC)     // 8192
#define QSZ (MTOT * DMOD)        // 8388608 elems per Q/K/V tensor

__device__ __half g_xf[MTOT * DMOD];
__device__ __half g_wf[4 * DMOD * DMOD];
__device__ __half g_qkv[3 * QSZ];
__device__ __half g_ao[MTOT * DMOD];

// ------------------------------ helpers -------------------------------------
__device__ __forceinline__ uint32_t su32(const void* p) {
    uint32_t a;
    asm("{ .reg .u64 t; cvta.to.shared.u64 t, %1; cvt.u32.u64 %0, t; }" : "=r"(a) : "l"(p));
    return a;
}
__device__ __forceinline__ uint32_t pk2h(float e0, float e1) {      // f16x2
    uint32_t d;
    asm("cvt.rn.f16x2.f32 %0, %1, %2;" : "=r"(d) : "f"(e1), "f"(e0));
    return d;
}
__device__ __forceinline__ void ldsm4(uint32_t& r0, uint32_t& r1, uint32_t& r2,
                                      uint32_t& r3, uint32_t a) {
    asm volatile("ldmatrix.sync.aligned.m8n8.x4.shared.b16 {%0,%1,%2,%3}, [%4];"
                 : "=r"(r0), "=r"(r1), "=r"(r2), "=r"(r3) : "r"(a));
}
__device__ __forceinline__ void ldsm4t(uint32_t& r0, uint32_t& r1, uint32_t& r2,
                                       uint32_t& r3, uint32_t a) {
    asm volatile("ldmatrix.sync.aligned.m8n8.x4.trans.shared.b16 {%0,%1,%2,%3}, [%4];"
                 : "=r"(r0), "=r"(r1), "=r"(r2), "=r"(r3) : "r"(a));
}
__device__ __forceinline__ void mmah(float* c, const uint32_t* a, const uint32_t* b) {
    asm volatile(
        "mma.sync.aligned.m16n8k16.row.col.f32.f16.f16.f32 "
        "{%0,%1,%2,%3},{%4,%5,%6,%7},{%8,%9},{%0,%1,%2,%3};"
        : "+f"(c[0]), "+f"(c[1]), "+f"(c[2]), "+f"(c[3])
        : "r"(a[0]), "r"(a[1]), "r"(a[2]), "r"(a[3]), "r"(b[0]), "r"(b[1]));
}
#define CP_ASYNC(dst, src) \
    asm volatile("cp.async.cg.shared.global [%0], [%1], 16;" :: "r"(dst), "l"(src) : "memory")
#define CP_COMMIT() asm volatile("cp.async.commit_group;" ::: "memory")
#define CP_WAIT(n)  asm volatile("cp.async.wait_group %0;" :: "n"(n) : "memory")

// --------------- fp32 -> fp16 convert, ALL tensors in one launch -------------
#define N4X (MTOT * DMOD / 4)
#define N4W (DMOD * DMOD / 4)

__global__ void split_all(const float4* __restrict__ x,
                          const float4* __restrict__ w0, const float4* __restrict__ w1,
                          const float4* __restrict__ w2, const float4* __restrict__ w3,
                          uint2* __restrict__ xf, uint2* __restrict__ wf) {
    int i = blockIdx.x * blockDim.x + threadIdx.x;
    const float4* src;
    uint2* dst;
    int off;
    if (i < N4X) {
        src = x; dst = xf; off = i;
    } else {
        int j = i - N4X;
        int wsel = j >> 18;
        off = j & (N4W - 1);
        src = (wsel == 0) ? w0 : (wsel == 1) ? w1 : (wsel == 2) ? w2 : w3;
        dst = wf + (size_t)wsel * N4W;
    }
    float4 v = src[off];
    dst[off] = make_uint2(pk2h(v.x, v.y), pk2h(v.z, v.w));
}

// ---------- GEMM: C[M,N] = A[M,1024] B[N,1024]^T, fp16, BK=64 (R14) ----------
#define GPB 144                   // 64 fp16 = 128B + 16B pad per row
#define ARR (128 * GPB)           // 18432 per array
#define BUF (2 * ARR)             // 36864 per stage

template <int MODE>                  // 1: fp16 QKV out (headsplit), 0: fp32 out
__global__ __launch_bounds__(256, 2) void gemm_h(const __half* __restrict__ A,
                                                 const __half* __restrict__ B,
                                                 float* __restrict__ C,
                                                 uint32_t* __restrict__ Oh) {
    extern __shared__ char sm[];
    const uint32_t sb = su32(sm);
    const int tid = threadIdx.x, lane = tid & 31, wid = tid >> 5;
    const int m0 = blockIdx.y * 128, n0 = blockIdx.x * 128;
    const int wm = (wid >> 2) * 64, wn = (wid & 3) * 32;

    auto fill = [&](int kb, int buf) {
        uint32_t base = sb + buf * BUF;
#pragma unroll
        for (int i = 0; i < 4; i++) {
            int idx = tid + i * 256;          // 0..1023
            int row = idx >> 3, c8 = idx & 7;
            uint32_t off = (uint32_t)row * GPB + c8 * 16;
            CP_ASYNC(base + 0 * ARR + off, A + (size_t)(m0 + row) * 1024 + kb + c8 * 8);
            CP_ASYNC(base + 1 * ARR + off, B + (size_t)(n0 + row) * 1024 + kb + c8 * 8);
        }
        CP_COMMIT();
    };

    float acc[4][4][4];
#pragma unroll
    for (int i = 0; i < 4; i++)
#pragma unroll
        for (int j = 0; j < 4; j++)
#pragma unroll
            for (int e = 0; e < 4; e++) acc[i][j][e] = 0.f;

    fill(0, 0);
    for (int t = 0; t < 16; t++) {
        if (t + 1 < 16) { fill((t + 1) * 64, (t + 1) & 1); CP_WAIT(1); }
        else            { CP_WAIT(0); }
        __syncthreads();

        const uint32_t bb = sb + (t & 1) * BUF;
#pragma unroll
        for (int s = 0; s < 4; s++) {
            uint32_t ah[4][4];
            const int arow = wm + (lane & 15);
            const int acol = s * 16 + (lane >> 4) * 8;
#pragma unroll
            for (int i = 0; i < 4; i++) {
                uint32_t off = (uint32_t)(arow + i * 16) * GPB + acol * 2;
                ldsm4(ah[i][0], ah[i][1], ah[i][2], ah[i][3], bb + 0 * ARR + off);
            }
            const int g = lane >> 3;
            const int brow = wn + (g >> 1) * 8 + (lane & 7);
            const int bcol = s * 16 + (g & 1) * 8;
#pragma unroll
            for (int p = 0; p < 2; p++) {
                uint32_t bh[4];
                uint32_t off = (uint32_t)(brow + p * 16) * GPB + bcol * 2;
                ldsm4(bh[0], bh[1], bh[2], bh[3], bb + 1 * ARR + off);
#pragma unroll
                for (int i = 0; i < 4; i++) mmah(acc[i][2 * p],     ah[i], &bh[0]);
#pragma unroll
                for (int i = 0; i < 4; i++) mmah(acc[i][2 * p + 1], ah[i], &bh[2]);
            }
        }
        __syncthreads();
    }

    const int r0 = m0 + wm + (lane >> 2);
    const int cb = n0 + wn + (lane & 3) * 2;
#pragma unroll
    for (int i = 0; i < 4; i++) {
#pragma unroll
        for (int half = 0; half < 2; half++) {
            int r = r0 + i * 16 + half * 8;
#pragma unroll
            for (int j = 0; j < 4; j++) {
                int c = cb + j * 8;
                float e0 = half ? acc[i][j][2] : acc[i][j][0];
                float e1 = half ? acc[i][j][3] : acc[i][j][1];
                if (MODE == 1) {
                    int which = c >> 10, cc = c & 1023;
                    int h = cc >> 6, dk = cc & 63;
                    int b = r >> 11, sdx = r & 2047;
                    size_t idx = (size_t)which * QSZ +
                                 ((((size_t)b * NHEAD + h) * SEQC + sdx) << 6) + dk;
                    Oh[idx >> 1] = pk2h(e0, e1);
                } else {
                    *(float2*)&C[(size_t)r * 1024 + c] = make_float2(e0, e1);
                }
            }
        }
    }
}

// -- flash attention, fp16 mma, causal; LPT heavy-first; 3-stage KV ring ------
#define AP 144
#define KVARR (64 * AP)          // 9216 per K or V array
#define STG (2 * KVARR)          // 18432 per KV stage
#define QREGA (128 * AP)         // 18432 fp16 Q tile

__global__ void attn_mma(const __half* __restrict__ QKV,
                         uint32_t* __restrict__ AO) {
    extern __shared__ char smc[];
    const uint32_t sb = su32(smc);
    const int tid = threadIdx.x, lane = tid & 31, w = tid >> 5;
    // LPT schedule: heaviest q-tiles (largest qt) launch first across all bh
    const int idx0 = blockIdx.x;
    const int qt = (SEQC / 128 - 1) - (idx0 >> 6);
    const int bh = idx0 & 63;
    const int q0 = qt * 128;
    const int b = bh >> 4, h = bh & 15;

    const size_t bhoff = (size_t)bh * SEQC * 64;
    const __half *Q = QKV + bhoff;
    const __half *K = QKV + QSZ + bhoff;
    const __half *V = QKV + 2 * QSZ + bhoff;

    auto fillkv = [&](int t, int buf) {
        uint32_t base = sb + QREGA + buf * STG;
#pragma unroll
        for (int i = 0; i < 2; i++) {
            int idx = tid + i * 256;
            int row = idx >> 3, c8 = idx & 7;
            uint32_t off = (uint32_t)row * AP + c8 * 16;
            size_t go = (size_t)(t * 64 + row) * 64 + c8 * 8;
            CP_ASYNC(base + 0 * KVARR + off, K + go);
            CP_ASYNC(base + 1 * KVARR + off, V + go);
        }
        CP_COMMIT();
    };

    const int tmax = 2 * qt + 1;

    fillkv(0, 0);
    if (tmax >= 1) fillkv(1, 1);
#pragma unroll
    for (int i = 0; i < 4; i++) {
        int idx = tid + i * 256;
        int row = idx >> 3, c8 = idx & 7;
        uint32_t off = (uint32_t)row * AP + c8 * 16;
        *(uint4*)(smc + off) = *(const uint4*)(Q + (size_t)(q0 + row) * 64 + c8 * 8);
    }
    __syncthreads();

    uint32_t qh[4][4];
    {
        const int arow = w * 16 + (lane & 15);
#pragma unroll
        for (int s = 0; s < 4; s++) {
            uint32_t off = (uint32_t)arow * AP + (s * 16 + (lane >> 4) * 8) * 2;
            ldsm4(qh[s][0], qh[s][1], qh[s][2], qh[s][3], sb + off);
        }
    }

    float o[8][4];
#pragma unroll
    for (int j = 0; j < 8; j++)
#pragma unroll
        for (int e = 0; e < 4; e++) o[j][e] = 0.f;
    float m_lo = -1e30f, m_hi = -1e30f, l_lo = 0.f, l_hi = 0.f;

    const int rlo = q0 + w * 16 + (lane >> 2);
    const int rhi = rlo + 8;
    const int g = lane >> 3;

    for (int t = 0; t <= tmax; t++) {
        if (t < tmax) { CP_WAIT(1); }       // group t complete, t+1 in flight
        else          { CP_WAIT(0); }
        __syncthreads();                    // single barrier per tile
        if (t + 2 <= tmax) fillkv(t + 2, (t + 2) % 3);

        const uint32_t bbase = sb + QREGA + (uint32_t)(t % 3) * STG;
        const uint32_t Ko = bbase, Vo = bbase + KVARR;

        float s_[8][4];
#pragma unroll
        for (int j = 0; j < 8; j++)
#pragma unroll
            for (int e = 0; e < 4; e++) s_[j][e] = 0.f;

#pragma unroll
        for (int s = 0; s < 4; s++) {
            const int brow = (g >> 1) * 8 + (lane & 7);
            const int bcol = s * 16 + (g & 1) * 8;
            uint32_t kh[4][4];
#pragma unroll
            for (int p = 0; p < 4; p++) {
                uint32_t off = (uint32_t)(brow + p * 16) * AP + bcol * 2;
                ldsm4(kh[p][0], kh[p][1], kh[p][2], kh[p][3], Ko + off);
            }
#pragma unroll
            for (int p = 0; p < 4; p++) {
                mmah(s_[2 * p],     qh[s], &kh[p][0]);
                mmah(s_[2 * p + 1], qh[s], &kh[p][2]);
            }
        }

        const bool msk = (t >= 2 * qt);
#pragma unroll
        for (int j = 0; j < 8; j++) {
            int c = t * 64 + j * 8 + (lane & 3) * 2;
#pragma unroll
            for (int e = 0; e < 4; e++) s_[j][e] *= 0.125f;
            if (msk) {
                if (c > rlo)     s_[j][0] = -1e30f;
                if (c + 1 > rlo) s_[j][1] = -1e30f;
                if (c > rhi)     s_[j][2] = -1e30f;
                if (c + 1 > rhi) s_[j][3] = -1e30f;
            }
        }

        float rm_lo = -1e30f, rm_hi = -1e30f;
#pragma unroll
        for (int j = 0; j < 8; j++) {
            rm_lo = fmaxf(rm_lo, fmaxf(s_[j][0], s_[j][1]));
            rm_hi = fmaxf(rm_hi, fmaxf(s_[j][2], s_[j][3]));
        }
        rm_lo = fmaxf(rm_lo, __shfl_xor_sync(0xffffffffu, rm_lo, 1));
        rm_lo = fmaxf(rm_lo, __shfl_xor_sync(0xffffffffu, rm_lo, 2));
        rm_hi = fmaxf(rm_hi, __shfl_xor_sync(0xffffffffu, rm_hi, 1));
        rm_hi = fmaxf(rm_hi, __shfl_xor_sync(0xffffffffu, rm_hi, 2));
        float mn_lo = fmaxf(m_lo, rm_lo), mn_hi = fmaxf(m_hi, rm_hi);
        float cor_lo = __expf(m_lo - mn_lo), cor_hi = __expf(m_hi - mn_hi);
        m_lo = mn_lo; m_hi = mn_hi;
        float sum_lo = 0.f, sum_hi = 0.f;
#pragma unroll
        for (int j = 0; j < 8; j++) {
            s_[j][0] = __expf(s_[j][0] - mn_lo); sum_lo += s_[j][0];
            s_[j][1] = __expf(s_[j][1] - mn_lo); sum_lo += s_[j][1];
            s_[j][2] = __expf(s_[j][2] - mn_hi); sum_hi += s_[j][2];
            s_[j][3] = __expf(s_[j][3] - mn_hi); sum_hi += s_[j][3];
        }
        sum_lo += __shfl_xor_sync(0xffffffffu, sum_lo, 1);
        sum_lo += __shfl_xor_sync(0xffffffffu, sum_lo, 2);
        sum_hi += __shfl_xor_sync(0xffffffffu, sum_hi, 1);
        sum_hi += __shfl_xor_sync(0xffffffffu, sum_hi, 2);
        l_lo = l_lo * cor_lo + sum_lo;
        l_hi = l_hi * cor_hi + sum_hi;
#pragma unroll
        for (int j = 0; j < 8; j++) {
            o[j][0] *= cor_lo; o[j][1] *= cor_lo;
            o[j][2] *= cor_hi; o[j][3] *= cor_hi;
        }

#pragma unroll
        for (int s = 0; s < 4; s++) {
            uint32_t ph[4];
            ph[0] = pk2h(s_[2 * s][0],     s_[2 * s][1]);
            ph[1] = pk2h(s_[2 * s][2],     s_[2 * s][3]);
            ph[2] = pk2h(s_[2 * s + 1][0], s_[2 * s + 1][1]);
            ph[3] = pk2h(s_[2 * s + 1][2], s_[2 * s + 1][3]);
            const int kvr = s * 16 + (g & 1) * 8 + (lane & 7);
            uint32_t vh[4][4];
#pragma unroll
            for (int p = 0; p < 4; p++) {
                uint32_t off = (uint32_t)kvr * AP + ((g >> 1) * 8 + p * 16) * 2;
                ldsm4t(vh[p][0], vh[p][1], vh[p][2], vh[p][3], Vo + off);
            }
#pragma unroll
            for (int p = 0; p < 4; p++) {
                mmah(o[2 * p],     ph, &vh[p][0]);
                mmah(o[2 * p + 1], ph, &vh[p][2]);
            }
        }
    }

    const float il_lo = 1.f / l_lo, il_hi = 1.f / l_hi;
    const int colb = h * 64 + (lane & 3) * 2;
#pragma unroll
    for (int j = 0; j < 8; j++) {
        int col = colb + j * 8;
        size_t ilo = ((size_t)(b * SEQC + rlo) * DMOD + col);
        size_t ihi = ((size_t)(b * SEQC + rhi) * DMOD + col);
        AO[ilo >> 1] = pk2h(o[j][0] * il_lo, o[j][1] * il_lo);
        AO[ihi >> 1] = pk2h(o[j][2] * il_hi, o[j][3] * il_hi);
    }
}

// ------------------------------ launch --------------------------------------
extern "C" void kernel_launch(void* const* d_in, const int* in_sizes, int n_in,
                              void* d_out, int out_size) {
    const float* x = (const float*)d_in[0];
    float* out = (float*)d_out;

    __half *xf, *wf, *qkv, *ao;
    cudaGetSymbolAddress((void**)&xf, g_xf);
    cudaGetSymbolAddress((void**)&wf, g_wf);
    cudaGetSymbolAddress((void**)&qkv, g_qkv);
    cudaGetSymbolAddress((void**)&ao, g_ao);

    const int NW = DMOD * DMOD;

    split_all<<<(N4X + 4 * N4W + 255) / 256, 256>>>(
        (const float4*)x, (const float4*)d_in[1], (const float4*)d_in[2],
        (const float4*)d_in[3], (const float4*)d_in[4],
        (uint2*)xf, (uint2*)wf);

    const int gshm = 2 * BUF;   // 73728
    cudaFuncSetAttribute(gemm_h<1>, cudaFuncAttributeMaxDynamicSharedMemorySize, gshm);
    cudaFuncSetAttribute(gemm_h<0>, cudaFuncAttributeMaxDynamicSharedMemorySize, gshm);

    // fused QKV projection: N = 3072, fp16 output
    gemm_h<1><<<dim3(24, 64), 256, gshm>>>(xf, wf, nullptr, (uint32_t*)qkv);

    const int ashm = QREGA + 3 * STG;   // 73728 (3-stage ring)
    cudaFuncSetAttribute(attn_mma, cudaFuncAttributeMaxDynamicSharedMemorySize, ashm);
    attn_mma<<<(SEQC / 128) * BATCHC * NHEAD, 256, ashm>>>(qkv, (uint32_t*)ao);

    gemm_h<0><<<dim3(8, 64), 256, gshm>>>(ao, wf + (size_t)3 * NW, out, nullptr);
}